// round 2
// baseline (speedup 1.0000x reference)
#include <cuda_runtime.h>
#include <cuda_bf16.h>
#include <cstdint>

#define N_NODES 50000
#define N_EDGES 800000
#define NGRAPHS 8
#define NCLASSES 10

// ---------------- scratch (device globals; no allocation allowed) ----------------
__device__ float g_h0 [N_NODES * 16];    // relu(x@fc0_w+b)
__device__ float g_xw1[N_NODES * 128];   // h0 @ w1  (heads-major: [h*32+c])
__device__ float g_agg1[N_NODES * 32];   // conv1 scatter accumulator
__device__ float g_cnt[N_NODES];         // in-degree (same for both convs)
__device__ float g_h1 [N_NODES * 32];    // relu(conv1)
__device__ float g_xw2[N_NODES * 256];   // h1 @ w2  ([h*64+c])
__device__ float g_agg2[N_NODES * 64];   // conv2 scatter accumulator
__device__ float g_pool[NGRAPHS * 64];   // per-graph feature sums
__device__ float g_gcnt[NGRAPHS];        // per-graph node counts

// ---------------- zero scratch (must re-zero every launch: graph replays) --------
__global__ void k_zero() {
    size_t idx = (size_t)blockIdx.x * blockDim.x + threadIdx.x;
    size_t stride = (size_t)gridDim.x * blockDim.x;
    for (size_t i = idx; i < (size_t)N_NODES * 64; i += stride) g_agg2[i] = 0.f;
    for (size_t i = idx; i < (size_t)N_NODES * 32; i += stride) g_agg1[i] = 0.f;
    for (size_t i = idx; i < (size_t)N_NODES;      i += stride) g_cnt[i]  = 0.f;
    if (idx < NGRAPHS * 64) g_pool[idx] = 0.f;
    if (idx < NGRAPHS)      g_gcnt[idx] = 0.f;
}

// ---------------- kernel A: h0 = relu(x@fc0_w+b);  xw1 = h0@w1 -------------------
// warp per node; w1 (16x128 = 8KB) staged in shared.
__global__ void k_fc0_xw1(const float* __restrict__ x,
                          const float* __restrict__ fc0_w,
                          const float* __restrict__ fc0_b,
                          const float* __restrict__ w1) {
    __shared__ float w1s[16 * 128];
    __shared__ float h0s[8][16];
    for (int i = threadIdx.x; i < 16 * 128; i += blockDim.x) w1s[i] = w1[i];
    __syncthreads();

    int w = threadIdx.x >> 5, lane = threadIdx.x & 31;
    int n = blockIdx.x * 8 + w;
    if (n >= N_NODES) return;

    if (lane < 16) {
        float acc = fc0_b[lane];
        #pragma unroll
        for (int j = 0; j < 3; j++) acc += x[n * 3 + j] * fc0_w[j * 16 + lane];
        acc = fmaxf(acc, 0.f);
        g_h0[n * 16 + lane] = acc;
        h0s[w][lane] = acc;
    }
    __syncwarp();

    float acc[4] = {0.f, 0.f, 0.f, 0.f};
    #pragma unroll
    for (int k = 0; k < 16; k++) {
        float hk = h0s[w][k];
        #pragma unroll
        for (int i = 0; i < 4; i++) acc[i] += hk * w1s[k * 128 + lane + 32 * i];
    }
    #pragma unroll
    for (int i = 0; i < 4; i++) g_xw1[(size_t)n * 128 + lane + 32 * i] = acc[i];
}

// ---------------- kernel B: conv1 edge pass --------------------------------------
// warp per edge: 16-dim diff, 4-head softmax, 32-out message, atomic scatter.
__global__ void k_conv1_edge(const int* __restrict__ ei,
                             const float* __restrict__ u1,
                             const float* __restrict__ c1) {
    __shared__ float u1s[64], c1s[4];
    if (threadIdx.x < 64) u1s[threadIdx.x] = u1[threadIdx.x];
    if (threadIdx.x < 4)  c1s[threadIdx.x] = c1[threadIdx.x];
    __syncthreads();

    int w = threadIdx.x >> 5, lane = threadIdx.x & 31;
    long long e = (long long)blockIdx.x * 8 + w;
    if (e >= N_EDGES) return;

    int s = ei[e];
    int t = ei[N_EDGES + e];

    int k = lane & 15;
    float d = g_h0[s * 16 + k] - g_h0[t * 16 + k];

    // lanes 0-15 reduce heads {0,1}; lanes 16-31 reduce heads {2,3}
    int hg = lane >> 4;
    float p0 = d * u1s[k * 4 + 2 * hg];
    float p1 = d * u1s[k * 4 + 2 * hg + 1];
    #pragma unroll
    for (int off = 8; off; off >>= 1) {
        p0 += __shfl_xor_sync(0xffffffffu, p0, off);
        p1 += __shfl_xor_sync(0xffffffffu, p1, off);
    }
    float l0 = __shfl_sync(0xffffffffu, p0, 0)  + c1s[0];
    float l1 = __shfl_sync(0xffffffffu, p1, 0)  + c1s[1];
    float l2 = __shfl_sync(0xffffffffu, p0, 16) + c1s[2];
    float l3 = __shfl_sync(0xffffffffu, p1, 16) + c1s[3];

    float m = fmaxf(fmaxf(l0, l1), fmaxf(l2, l3));
    float q0 = __expf(l0 - m), q1 = __expf(l1 - m), q2 = __expf(l2 - m), q3 = __expf(l3 - m);
    float inv = 1.f / (q0 + q1 + q2 + q3);
    q0 *= inv; q1 *= inv; q2 *= inv; q3 *= inv;

    const float* xr = g_xw1 + (size_t)s * 128;
    float msg = q0 * xr[lane] + q1 * xr[32 + lane] + q2 * xr[64 + lane] + q3 * xr[96 + lane];
    atomicAdd(&g_agg1[(size_t)t * 32 + lane], msg);
    if (lane == 0) atomicAdd(&g_cnt[t], 1.0f);
}

// ---------------- kernel C: h1 = relu(agg1/cnt + b1);  xw2 = h1@w2 ---------------
// warp per node; w2 (32x256 = 32KB) staged in shared.
__global__ void k_conv1_epi_xw2(const float* __restrict__ b1,
                                const float* __restrict__ w2) {
    __shared__ float w2s[32 * 256];
    for (int i = threadIdx.x; i < 32 * 256; i += blockDim.x) w2s[i] = w2[i];
    __syncthreads();

    int w = threadIdx.x >> 5, lane = threadIdx.x & 31;
    int n = blockIdx.x * 8 + w;
    if (n >= N_NODES) return;

    float cnt = fmaxf(g_cnt[n], 1.f);
    float h = g_agg1[(size_t)n * 32 + lane] / cnt + b1[lane];
    h = fmaxf(h, 0.f);
    g_h1[(size_t)n * 32 + lane] = h;

    float acc[8] = {0.f, 0.f, 0.f, 0.f, 0.f, 0.f, 0.f, 0.f};
    #pragma unroll
    for (int k = 0; k < 32; k++) {
        float hk = __shfl_sync(0xffffffffu, h, k);
        #pragma unroll
        for (int i = 0; i < 8; i++) acc[i] += hk * w2s[k * 256 + lane + 32 * i];
    }
    #pragma unroll
    for (int i = 0; i < 8; i++) g_xw2[(size_t)n * 256 + lane + 32 * i] = acc[i];
}

// ---------------- kernel D: conv2 edge pass --------------------------------------
// warp per edge: 32-dim diff (1 per lane), 4-head softmax, 64-out message.
__global__ void k_conv2_edge(const int* __restrict__ ei,
                             const float* __restrict__ u2,
                             const float* __restrict__ c2) {
    __shared__ float u2s[128], c2s[4];
    if (threadIdx.x < 128) u2s[threadIdx.x] = u2[threadIdx.x];
    if (threadIdx.x < 4)   c2s[threadIdx.x] = c2[threadIdx.x];
    __syncthreads();

    int w = threadIdx.x >> 5, lane = threadIdx.x & 31;
    long long e = (long long)blockIdx.x * 8 + w;
    if (e >= N_EDGES) return;

    int s = ei[e];
    int t = ei[N_EDGES + e];

    float d = g_h1[(size_t)s * 32 + lane] - g_h1[(size_t)t * 32 + lane];
    float p0 = d * u2s[lane * 4 + 0];
    float p1 = d * u2s[lane * 4 + 1];
    float p2 = d * u2s[lane * 4 + 2];
    float p3 = d * u2s[lane * 4 + 3];
    #pragma unroll
    for (int off = 16; off; off >>= 1) {
        p0 += __shfl_xor_sync(0xffffffffu, p0, off);
        p1 += __shfl_xor_sync(0xffffffffu, p1, off);
        p2 += __shfl_xor_sync(0xffffffffu, p2, off);
        p3 += __shfl_xor_sync(0xffffffffu, p3, off);
    }
    p0 += c2s[0]; p1 += c2s[1]; p2 += c2s[2]; p3 += c2s[3];

    float m = fmaxf(fmaxf(p0, p1), fmaxf(p2, p3));
    float q0 = __expf(p0 - m), q1 = __expf(p1 - m), q2 = __expf(p2 - m), q3 = __expf(p3 - m);
    float inv = 1.f / (q0 + q1 + q2 + q3);
    q0 *= inv; q1 *= inv; q2 *= inv; q3 *= inv;

    const float* xr = g_xw2 + (size_t)s * 256;
    float m0 = q0 * xr[lane]      + q1 * xr[64 + lane]  + q2 * xr[128 + lane] + q3 * xr[192 + lane];
    float m1 = q0 * xr[32 + lane] + q1 * xr[96 + lane]  + q2 * xr[160 + lane] + q3 * xr[224 + lane];
    atomicAdd(&g_agg2[(size_t)t * 64 + lane],      m0);
    atomicAdd(&g_agg2[(size_t)t * 64 + 32 + lane], m1);
}

// ---------------- kernel E: h2 = relu(agg2/cnt + b2); staged global pooling ------
__global__ void k_conv2_epi_pool(const float* __restrict__ b2,
                                 const int* __restrict__ batch) {
    __shared__ float pools[NGRAPHS * 64];
    __shared__ float gcnts[NGRAPHS];
    for (int i = threadIdx.x; i < NGRAPHS * 64; i += blockDim.x) pools[i] = 0.f;
    if (threadIdx.x < NGRAPHS) gcnts[threadIdx.x] = 0.f;
    __syncthreads();

    int w = threadIdx.x >> 5, lane = threadIdx.x & 31;
    int n = blockIdx.x * 8 + w;
    if (n < N_NODES) {
        float cnt = fmaxf(g_cnt[n], 1.f);
        int g = batch[n];
        float h0v = fmaxf(g_agg2[(size_t)n * 64 + lane]      / cnt + b2[lane],      0.f);
        float h1v = fmaxf(g_agg2[(size_t)n * 64 + 32 + lane] / cnt + b2[32 + lane], 0.f);
        atomicAdd(&pools[g * 64 + lane],      h0v);
        atomicAdd(&pools[g * 64 + 32 + lane], h1v);
        if (lane == 0) atomicAdd(&gcnts[g], 1.f);
    }
    __syncthreads();
    for (int i = threadIdx.x; i < NGRAPHS * 64; i += blockDim.x) atomicAdd(&g_pool[i], pools[i]);
    if (threadIdx.x < NGRAPHS) atomicAdd(&g_gcnt[threadIdx.x], gcnts[threadIdx.x]);
}

// ---------------- kernel F: out = (pool/gcnt) @ fc1_w + fc1_b --------------------
__global__ void k_head(const float* __restrict__ fc1_w,
                       const float* __restrict__ fc1_b,
                       float* __restrict__ out) {
    int tid = threadIdx.x;
    if (tid < NGRAPHS * NCLASSES) {
        int g = tid / NCLASSES, j = tid % NCLASSES;
        float invn = 1.f / fmaxf(g_gcnt[g], 1.f);
        float acc = 0.f;
        #pragma unroll
        for (int c = 0; c < 64; c++) acc += g_pool[g * 64 + c] * fc1_w[c * NCLASSES + j];
        out[tid] = acc * invn + fc1_b[j];
    }
}

// ---------------- launch ----------------------------------------------------------
extern "C" void kernel_launch(void* const* d_in, const int* in_sizes, int n_in,
                              void* d_out, int out_size) {
    const float* x     = (const float*)d_in[0];
    const int*   ei    = (const int*)d_in[1];
    const int*   batch = (const int*)d_in[2];
    const float* fc0_w = (const float*)d_in[3];
    const float* fc0_b = (const float*)d_in[4];
    const float* u1    = (const float*)d_in[5];
    const float* c1    = (const float*)d_in[6];
    const float* w1    = (const float*)d_in[7];
    const float* b1    = (const float*)d_in[8];
    const float* u2    = (const float*)d_in[9];
    const float* c2    = (const float*)d_in[10];
    const float* w2    = (const float*)d_in[11];
    const float* b2    = (const float*)d_in[12];
    const float* fc1_w = (const float*)d_in[13];
    const float* fc1_b = (const float*)d_in[14];
    float* out = (float*)d_out;

    k_zero<<<2048, 256>>>();
    k_fc0_xw1<<<(N_NODES + 7) / 8, 256>>>(x, fc0_w, fc0_b, w1);
    k_conv1_edge<<<(N_EDGES + 7) / 8, 256>>>(ei, u1, c1);
    k_conv1_epi_xw2<<<(N_NODES + 7) / 8, 256>>>(b1, w2);
    k_conv2_edge<<<(N_EDGES + 7) / 8, 256>>>(ei, u2, c2);
    k_conv2_epi_pool<<<(N_NODES + 7) / 8, 256>>>(b2, batch);
    k_head<<<1, 128>>>(fc1_w, fc1_b, out);
}

// round 3
// speedup vs baseline: 1.1630x; 1.1630x over previous
#include <cuda_runtime.h>
#include <cuda_fp16.h>
#include <cstdint>

#define N_NODES 50000
#define N_EDGES 800000
#define NGRAPHS 8
#define NCLASSES 10

// ---------------- scratch (device globals) ----------------------------------------
__device__ float   g_h0  [N_NODES * 16];   // relu(x@fc0_w+b)   fp32
__device__ __half2 g_xw1h[N_NODES * 64];   // h0@w1, pair-interleaved: [h*16+l] = (ch 2l, 2l+1) of head h (32ch/head... see note)
__device__ float   g_agg1[N_NODES * 32];
__device__ float   g_cnt [N_NODES];
__device__ float   g_h1  [N_NODES * 32];   // fp32 (used for diffs)
__device__ __half2 g_xw2h[N_NODES * 128];  // h1@w2, [h*32+l] = (ch h*64+2l, +1)
__device__ float   g_agg2[N_NODES * 64];
__device__ float   g_pool[NGRAPHS * 64];
__device__ float   g_gcnt[NGRAPHS];

// ---------------- zero scratch -----------------------------------------------------
__global__ void k_zero() {
    size_t idx = (size_t)blockIdx.x * blockDim.x + threadIdx.x;
    size_t stride = (size_t)gridDim.x * blockDim.x;
    for (size_t i = idx; i < (size_t)N_NODES * 64; i += stride) g_agg2[i] = 0.f;
    for (size_t i = idx; i < (size_t)N_NODES * 32; i += stride) g_agg1[i] = 0.f;
    for (size_t i = idx; i < (size_t)N_NODES;      i += stride) g_cnt[i]  = 0.f;
    if (idx < NGRAPHS * 64) g_pool[idx] = 0.f;
    if (idx < NGRAPHS)      g_gcnt[idx] = 0.f;
}

// ---------------- kernel A: h0 = relu(x@fc0+b); xw1 = h0@w1 (4 nodes/warp) --------
// w1 viewed as float2[16*64]: index k*64 + j, j in [0,64) = channel pair (2j,2j+1).
__global__ void k_fc0_xw1(const float* __restrict__ x,
                          const float* __restrict__ fc0_w,
                          const float* __restrict__ fc0_b,
                          const float* __restrict__ w1) {
    __shared__ float2 w1s[16 * 64];        // 8KB
    const float2* w1g = (const float2*)w1;
    for (int i = threadIdx.x; i < 16 * 64; i += blockDim.x) w1s[i] = w1g[i];
    __syncthreads();

    int w = threadIdx.x >> 5, lane = threadIdx.x & 31;
    int n0 = (blockIdx.x * 8 + w) * 4;
    if (n0 >= N_NODES) return;

    float hn[4];
    #pragma unroll
    for (int m = 0; m < 4; m++) {
        int n = n0 + m;
        float v = 0.f;
        if (n < N_NODES && lane < 16) {
            v = fc0_b[lane];
            #pragma unroll
            for (int j = 0; j < 3; j++) v += x[n * 3 + j] * fc0_w[j * 16 + lane];
            v = fmaxf(v, 0.f);
            g_h0[n * 16 + lane] = v;
        }
        hn[m] = v;
    }
    __syncwarp();

    float2 acc[4][2];
    #pragma unroll
    for (int m = 0; m < 4; m++) { acc[m][0] = make_float2(0.f, 0.f); acc[m][1] = make_float2(0.f, 0.f); }

    #pragma unroll
    for (int k = 0; k < 16; k++) {
        float2 wk0 = w1s[k * 64 + lane];
        float2 wk1 = w1s[k * 64 + 32 + lane];
        #pragma unroll
        for (int m = 0; m < 4; m++) {
            float hk = __shfl_sync(0xffffffffu, hn[m], k);
            acc[m][0].x += hk * wk0.x; acc[m][0].y += hk * wk0.y;
            acc[m][1].x += hk * wk1.x; acc[m][1].y += hk * wk1.y;
        }
    }
    #pragma unroll
    for (int m = 0; m < 4; m++) {
        int n = n0 + m;
        if (n < N_NODES) {
            g_xw1h[(size_t)n * 64 + lane]      = __float22half2_rn(acc[m][0]);
            g_xw1h[(size_t)n * 64 + 32 + lane] = __float22half2_rn(acc[m][1]);
        }
    }
}

// ---------------- kernel B: conv1 edge pass ---------------------------------------
// warp/edge. Channel pair j of head h lives at xw1h[s*64 + h*16 + j], j<16.
__global__ void k_conv1_edge(const int* __restrict__ ei,
                             const float* __restrict__ u1,
                             const float* __restrict__ c1) {
    __shared__ float u1s[64], c1s[4];
    if (threadIdx.x < 64) u1s[threadIdx.x] = u1[threadIdx.x];
    if (threadIdx.x < 4)  c1s[threadIdx.x] = c1[threadIdx.x];
    __syncthreads();

    int w = threadIdx.x >> 5, lane = threadIdx.x & 31;
    int e = blockIdx.x * 8 + w;
    if (e >= N_EDGES) return;

    int s = ei[e];
    int t = ei[N_EDGES + e];

    int k = lane & 15;
    float d = g_h0[s * 16 + k] - g_h0[t * 16 + k];

    int hg = lane >> 4;
    float p0 = d * u1s[k * 4 + 2 * hg];
    float p1 = d * u1s[k * 4 + 2 * hg + 1];
    #pragma unroll
    for (int off = 8; off; off >>= 1) {
        p0 += __shfl_xor_sync(0xffffffffu, p0, off);
        p1 += __shfl_xor_sync(0xffffffffu, p1, off);
    }
    float l0 = __shfl_sync(0xffffffffu, p0, 0)  + c1s[0];
    float l1 = __shfl_sync(0xffffffffu, p1, 0)  + c1s[1];
    float l2 = __shfl_sync(0xffffffffu, p0, 16) + c1s[2];
    float l3 = __shfl_sync(0xffffffffu, p1, 16) + c1s[3];

    float m = fmaxf(fmaxf(l0, l1), fmaxf(l2, l3));
    float q0 = __expf(l0 - m), q1 = __expf(l1 - m), q2 = __expf(l2 - m), q3 = __expf(l3 - m);
    float inv = 1.f / (q0 + q1 + q2 + q3);
    q0 *= inv; q1 *= inv; q2 *= inv; q3 *= inv;

    if (lane < 16) {
        const __half2* xr = g_xw1h + (size_t)s * 64;
        float2 v0 = __half22float2(xr[lane]);
        float2 v1 = __half22float2(xr[16 + lane]);
        float2 v2 = __half22float2(xr[32 + lane]);
        float2 v3 = __half22float2(xr[48 + lane]);
        float2 msg;
        msg.x = q0 * v0.x + q1 * v1.x + q2 * v2.x + q3 * v3.x;
        msg.y = q0 * v0.y + q1 * v1.y + q2 * v2.y + q3 * v3.y;
        atomicAdd((float2*)&g_agg1[(size_t)t * 32 + 2 * lane], msg);
    }
    if (lane == 0) atomicAdd(&g_cnt[t], 1.0f);
}

// ---------------- kernel C: h1 epilogue + xw2 = h1@w2 (4 nodes/warp) --------------
// w2 viewed as float2[32*128]: index k*128 + (h*32+l) = channel pair (h*64+2l, +1).
__global__ void k_conv1_epi_xw2(const float* __restrict__ b1,
                                const float* __restrict__ w2) {
    __shared__ float2 w2s[32 * 128];       // 32KB
    const float2* w2g = (const float2*)w2;
    for (int i = threadIdx.x; i < 32 * 128; i += blockDim.x) w2s[i] = w2g[i];
    __syncthreads();

    int w = threadIdx.x >> 5, lane = threadIdx.x & 31;
    int n0 = (blockIdx.x * 8 + w) * 4;
    if (n0 >= N_NODES) return;

    float hn[4];
    #pragma unroll
    for (int m = 0; m < 4; m++) {
        int n = n0 + m;
        float h = 0.f;
        if (n < N_NODES) {
            float cnt = fmaxf(g_cnt[n], 1.f);
            h = fmaxf(g_agg1[(size_t)n * 32 + lane] / cnt + b1[lane], 0.f);
            g_h1[(size_t)n * 32 + lane] = h;
        }
        hn[m] = h;
    }
    __syncwarp();

    float2 acc[4][4];
    #pragma unroll
    for (int m = 0; m < 4; m++)
        #pragma unroll
        for (int h = 0; h < 4; h++) acc[m][h] = make_float2(0.f, 0.f);

    #pragma unroll
    for (int k = 0; k < 32; k++) {
        float2 wk[4];
        #pragma unroll
        for (int h = 0; h < 4; h++) wk[h] = w2s[k * 128 + h * 32 + lane];
        #pragma unroll
        for (int m = 0; m < 4; m++) {
            float hk = __shfl_sync(0xffffffffu, hn[m], k);
            #pragma unroll
            for (int h = 0; h < 4; h++) {
                acc[m][h].x += hk * wk[h].x;
                acc[m][h].y += hk * wk[h].y;
            }
        }
    }
    #pragma unroll
    for (int m = 0; m < 4; m++) {
        int n = n0 + m;
        if (n < N_NODES) {
            #pragma unroll
            for (int h = 0; h < 4; h++)
                g_xw2h[(size_t)n * 128 + h * 32 + lane] = __float22half2_rn(acc[m][h]);
        }
    }
}

// ---------------- kernel D: conv2 edge pass ---------------------------------------
__global__ void k_conv2_edge(const int* __restrict__ ei,
                             const float* __restrict__ u2,
                             const float* __restrict__ c2) {
    __shared__ float u2s[128], c2s[4];
    if (threadIdx.x < 128) u2s[threadIdx.x] = u2[threadIdx.x];
    if (threadIdx.x < 4)   c2s[threadIdx.x] = c2[threadIdx.x];
    __syncthreads();

    int w = threadIdx.x >> 5, lane = threadIdx.x & 31;
    int e = blockIdx.x * 8 + w;
    if (e >= N_EDGES) return;

    int s = ei[e];
    int t = ei[N_EDGES + e];

    float d = g_h1[(size_t)s * 32 + lane] - g_h1[(size_t)t * 32 + lane];
    float p0 = d * u2s[lane * 4 + 0];
    float p1 = d * u2s[lane * 4 + 1];
    float p2 = d * u2s[lane * 4 + 2];
    float p3 = d * u2s[lane * 4 + 3];
    #pragma unroll
    for (int off = 16; off; off >>= 1) {
        p0 += __shfl_xor_sync(0xffffffffu, p0, off);
        p1 += __shfl_xor_sync(0xffffffffu, p1, off);
        p2 += __shfl_xor_sync(0xffffffffu, p2, off);
        p3 += __shfl_xor_sync(0xffffffffu, p3, off);
    }
    p0 += c2s[0]; p1 += c2s[1]; p2 += c2s[2]; p3 += c2s[3];

    float m = fmaxf(fmaxf(p0, p1), fmaxf(p2, p3));
    float q0 = __expf(p0 - m), q1 = __expf(p1 - m), q2 = __expf(p2 - m), q3 = __expf(p3 - m);
    float inv = 1.f / (q0 + q1 + q2 + q3);
    q0 *= inv; q1 *= inv; q2 *= inv; q3 *= inv;

    const __half2* xr = g_xw2h + (size_t)s * 128;
    float2 v0 = __half22float2(xr[lane]);
    float2 v1 = __half22float2(xr[32 + lane]);
    float2 v2 = __half22float2(xr[64 + lane]);
    float2 v3 = __half22float2(xr[96 + lane]);
    float2 msg;
    msg.x = q0 * v0.x + q1 * v1.x + q2 * v2.x + q3 * v3.x;
    msg.y = q0 * v0.y + q1 * v1.y + q2 * v2.y + q3 * v3.y;
    atomicAdd((float2*)&g_agg2[(size_t)t * 64 + 2 * lane], msg);
}

// ---------------- kernel E: h2 epilogue + staged global pooling --------------------
__global__ void k_conv2_epi_pool(const float* __restrict__ b2,
                                 const int* __restrict__ batch) {
    __shared__ float pools[NGRAPHS * 64];
    __shared__ float gcnts[NGRAPHS];
    for (int i = threadIdx.x; i < NGRAPHS * 64; i += blockDim.x) pools[i] = 0.f;
    if (threadIdx.x < NGRAPHS) gcnts[threadIdx.x] = 0.f;
    __syncthreads();

    int w = threadIdx.x >> 5, lane = threadIdx.x & 31;
    int n = blockIdx.x * 8 + w;
    if (n < N_NODES) {
        float cnt = fmaxf(g_cnt[n], 1.f);
        int g = batch[n];
        float h0v = fmaxf(g_agg2[(size_t)n * 64 + lane]      / cnt + b2[lane],      0.f);
        float h1v = fmaxf(g_agg2[(size_t)n * 64 + 32 + lane] / cnt + b2[32 + lane], 0.f);
        atomicAdd(&pools[g * 64 + lane],      h0v);
        atomicAdd(&pools[g * 64 + 32 + lane], h1v);
        if (lane == 0) atomicAdd(&gcnts[g], 1.f);
    }
    __syncthreads();
    for (int i = threadIdx.x; i < NGRAPHS * 64; i += blockDim.x) atomicAdd(&g_pool[i], pools[i]);
    if (threadIdx.x < NGRAPHS) atomicAdd(&g_gcnt[threadIdx.x], gcnts[threadIdx.x]);
}

// ---------------- kernel F: head ---------------------------------------------------
__global__ void k_head(const float* __restrict__ fc1_w,
                       const float* __restrict__ fc1_b,
                       float* __restrict__ out) {
    int tid = threadIdx.x;
    if (tid < NGRAPHS * NCLASSES) {
        int g = tid / NCLASSES, j = tid % NCLASSES;
        float invn = 1.f / fmaxf(g_gcnt[g], 1.f);
        float acc = 0.f;
        #pragma unroll
        for (int c = 0; c < 64; c++) acc += g_pool[g * 64 + c] * fc1_w[c * NCLASSES + j];
        out[tid] = acc * invn + fc1_b[j];
    }
}

// ---------------- launch ------------------------------------------------------------
extern "C" void kernel_launch(void* const* d_in, const int* in_sizes, int n_in,
                              void* d_out, int out_size) {
    const float* x     = (const float*)d_in[0];
    const int*   ei    = (const int*)d_in[1];
    const int*   batch = (const int*)d_in[2];
    const float* fc0_w = (const float*)d_in[3];
    const float* fc0_b = (const float*)d_in[4];
    const float* u1    = (const float*)d_in[5];
    const float* c1    = (const float*)d_in[6];
    const float* w1    = (const float*)d_in[7];
    const float* b1    = (const float*)d_in[8];
    const float* u2    = (const float*)d_in[9];
    const float* c2    = (const float*)d_in[10];
    const float* w2    = (const float*)d_in[11];
    const float* b2    = (const float*)d_in[12];
    const float* fc1_w = (const float*)d_in[13];
    const float* fc1_b = (const float*)d_in[14];
    float* out = (float*)d_out;

    k_zero<<<2048, 256>>>();
    k_fc0_xw1<<<(N_NODES + 31) / 32, 256>>>(x, fc0_w, fc0_b, w1);
    k_conv1_edge<<<(N_EDGES + 7) / 8, 256>>>(ei, u1, c1);
    k_conv1_epi_xw2<<<(N_NODES + 31) / 32, 256>>>(b1, w2);
    k_conv2_edge<<<(N_EDGES + 7) / 8, 256>>>(ei, u2, c2);
    k_conv2_epi_pool<<<(N_NODES + 7) / 8, 256>>>(b2, batch);
    k_head<<<1, 128>>>(fc1_w, fc1_b, out);
}

// round 4
// speedup vs baseline: 1.6507x; 1.4193x over previous
#include <cuda_runtime.h>
#include <cuda_fp16.h>
#include <cstdint>

#define N_NODES 50000
#define N_EDGES 800000
#define NGRAPHS 8
#define NCLASSES 10

// ---------------- scratch (device globals) ----------------------------------------
__device__ float   g_h0  [N_NODES * 16];
__device__ float4  g_hu1 [N_NODES];        // h0 @ u1  (4 head logit contributions)
__device__ __half2 g_xw1h[N_NODES * 64];   // h0@w1, [h*16+j] = head h, channel pair (2j,2j+1)
__device__ float   g_agg1[N_NODES * 32];
__device__ float   g_cnt [N_NODES];
__device__ float4  g_hu2 [N_NODES];        // h1 @ u2
__device__ __half2 g_xw2h[N_NODES * 128];  // h1@w2, [h*32+l] = head h, channel pair (2l,2l+1)
__device__ float   g_agg2[N_NODES * 64];
__device__ float   g_pool[NGRAPHS * 64];
__device__ float   g_gcnt[NGRAPHS];

// ---------------- zero scratch -----------------------------------------------------
__global__ void k_zero() {
    size_t idx = (size_t)blockIdx.x * blockDim.x + threadIdx.x;
    size_t stride = (size_t)gridDim.x * blockDim.x;
    for (size_t i = idx; i < (size_t)N_NODES * 64; i += stride) g_agg2[i] = 0.f;
    for (size_t i = idx; i < (size_t)N_NODES * 32; i += stride) g_agg1[i] = 0.f;
    for (size_t i = idx; i < (size_t)N_NODES;      i += stride) g_cnt[i]  = 0.f;
    if (idx < NGRAPHS * 64) g_pool[idx] = 0.f;
    if (idx < NGRAPHS)      g_gcnt[idx] = 0.f;
}

// ---------------- kernel A: h0 = relu(x@fc0+b); xw1 = h0@w1; hu1 = h0@u1 ----------
__global__ void k_fc0_xw1(const float* __restrict__ x,
                          const float* __restrict__ fc0_w,
                          const float* __restrict__ fc0_b,
                          const float* __restrict__ w1,
                          const float* __restrict__ u1) {
    __shared__ float2 w1s[16 * 64];        // 8KB
    __shared__ float  u1s[64];
    const float2* w1g = (const float2*)w1;
    for (int i = threadIdx.x; i < 16 * 64; i += blockDim.x) w1s[i] = w1g[i];
    if (threadIdx.x < 64) u1s[threadIdx.x] = u1[threadIdx.x];
    __syncthreads();

    int w = threadIdx.x >> 5, lane = threadIdx.x & 31;
    int n0 = (blockIdx.x * 8 + w) * 4;
    if (n0 >= N_NODES) return;

    float hn[4];
    #pragma unroll
    for (int m = 0; m < 4; m++) {
        int n = n0 + m;
        float v = 0.f;
        if (n < N_NODES && lane < 16) {
            v = fc0_b[lane];
            #pragma unroll
            for (int j = 0; j < 3; j++) v += x[n * 3 + j] * fc0_w[j * 16 + lane];
            v = fmaxf(v, 0.f);
            g_h0[n * 16 + lane] = v;
        }
        hn[m] = v;
    }
    __syncwarp();

    // hu1[n] = h0[n] @ u1 : lane k (<16) contributes v*u1[k*4+h]; reduce.
    #pragma unroll
    for (int m = 0; m < 4; m++) {
        int n = n0 + m;
        if (n >= N_NODES) break;
        int k = lane & 15;
        float a0 = hn[m] * u1s[k * 4 + 0];
        float a1 = hn[m] * u1s[k * 4 + 1];
        float a2 = hn[m] * u1s[k * 4 + 2];
        float a3 = hn[m] * u1s[k * 4 + 3];
        #pragma unroll
        for (int off = 16; off; off >>= 1) {
            a0 += __shfl_xor_sync(0xffffffffu, a0, off);
            a1 += __shfl_xor_sync(0xffffffffu, a1, off);
            a2 += __shfl_xor_sync(0xffffffffu, a2, off);
            a3 += __shfl_xor_sync(0xffffffffu, a3, off);
        }
        // lanes >=16 have hn=0 so they contribute nothing; sum counts lanes 0..15 once
        // (xor tree over 32 lanes double-counts? no: each lane's own term appears once)
        if (lane == 0) g_hu1[n] = make_float4(a0 * 0.5f, a1 * 0.5f, a2 * 0.5f, a3 * 0.5f);
    }
    // NOTE: correction below — see recompute without the 0.5 hack.

    float2 acc[4][2];
    #pragma unroll
    for (int m = 0; m < 4; m++) { acc[m][0] = make_float2(0.f, 0.f); acc[m][1] = make_float2(0.f, 0.f); }

    #pragma unroll
    for (int k = 0; k < 16; k++) {
        float2 wk0 = w1s[k * 64 + lane];
        float2 wk1 = w1s[k * 64 + 32 + lane];
        #pragma unroll
        for (int m = 0; m < 4; m++) {
            float hk = __shfl_sync(0xffffffffu, hn[m], k);
            acc[m][0].x += hk * wk0.x; acc[m][0].y += hk * wk0.y;
            acc[m][1].x += hk * wk1.x; acc[m][1].y += hk * wk1.y;
        }
    }
    #pragma unroll
    for (int m = 0; m < 4; m++) {
        int n = n0 + m;
        if (n < N_NODES) {
            g_xw1h[(size_t)n * 64 + lane]      = __float22half2_rn(acc[m][0]);
            g_xw1h[(size_t)n * 64 + 32 + lane] = __float22half2_rn(acc[m][1]);
        }
    }
}

// Fix for hu1: the xor-tree over 32 lanes with zeros in lanes>=16 sums each of the
// 16 terms exactly once (no double count). The 0.5 scaling above would be WRONG.
// To keep things simple and obviously correct, recompute hu1 in a dedicated tiny
// kernel: one warp handles 2 nodes (16 lanes each), pure reads of g_h0.
__global__ void k_hu1(const float* __restrict__ u1) {
    __shared__ float u1s[64];
    if (threadIdx.x < 64) u1s[threadIdx.x] = u1[threadIdx.x];
    __syncthreads();
    int w = threadIdx.x >> 5, lane = threadIdx.x & 31;
    int sub = lane >> 4, k = lane & 15;
    int n = (blockIdx.x * 8 + w) * 2 + sub;
    if (n >= N_NODES) return;
    float v = g_h0[n * 16 + k];
    float a0 = v * u1s[k * 4 + 0];
    float a1 = v * u1s[k * 4 + 1];
    float a2 = v * u1s[k * 4 + 2];
    float a3 = v * u1s[k * 4 + 3];
    #pragma unroll
    for (int off = 8; off; off >>= 1) {
        a0 += __shfl_xor_sync(0xffffffffu, a0, off);
        a1 += __shfl_xor_sync(0xffffffffu, a1, off);
        a2 += __shfl_xor_sync(0xffffffffu, a2, off);
        a3 += __shfl_xor_sync(0xffffffffu, a3, off);
    }
    if (k == 0) g_hu1[n] = make_float4(a0, a1, a2, a3);
}

// ---------------- kernel B: conv1 edge pass (2 edges per warp) ---------------------
__global__ void k_conv1_edge(const int* __restrict__ ei,
                             const float* __restrict__ c1) {
    float cc0 = __ldg(&c1[0]), cc1 = __ldg(&c1[1]), cc2 = __ldg(&c1[2]), cc3 = __ldg(&c1[3]);
    int w = threadIdx.x >> 5, lane = threadIdx.x & 31;
    int sub = lane >> 4, j = lane & 15;
    int e = (blockIdx.x * 8 + w) * 2 + sub;
    if (e >= N_EDGES) return;

    int s = ei[e];
    int t = ei[N_EDGES + e];

    float4 a = g_hu1[s];
    float4 b = g_hu1[t];
    float l0 = a.x - b.x + cc0;
    float l1 = a.y - b.y + cc1;
    float l2 = a.z - b.z + cc2;
    float l3 = a.w - b.w + cc3;

    float m = fmaxf(fmaxf(l0, l1), fmaxf(l2, l3));
    float q0 = __expf(l0 - m), q1 = __expf(l1 - m), q2 = __expf(l2 - m), q3 = __expf(l3 - m);
    float inv = 1.f / (q0 + q1 + q2 + q3);
    q0 *= inv; q1 *= inv; q2 *= inv; q3 *= inv;

    const __half2* xr = g_xw1h + (size_t)s * 64;
    float2 v0 = __half22float2(xr[j]);
    float2 v1 = __half22float2(xr[16 + j]);
    float2 v2 = __half22float2(xr[32 + j]);
    float2 v3 = __half22float2(xr[48 + j]);
    float2 msg;
    msg.x = q0 * v0.x + q1 * v1.x + q2 * v2.x + q3 * v3.x;
    msg.y = q0 * v0.y + q1 * v1.y + q2 * v2.y + q3 * v3.y;
    atomicAdd((float2*)&g_agg1[(size_t)t * 32 + 2 * j], msg);
    if (j == 0) atomicAdd(&g_cnt[t], 1.0f);
}

// ---------------- kernel C: h1 epilogue + xw2 = h1@w2 + hu2 = h1@u2 ----------------
__global__ void k_conv1_epi_xw2(const float* __restrict__ b1,
                                const float* __restrict__ w2,
                                const float* __restrict__ u2) {
    __shared__ float2 w2s[32 * 128];       // 32KB
    __shared__ float  u2s[128];
    const float2* w2g = (const float2*)w2;
    for (int i = threadIdx.x; i < 32 * 128; i += blockDim.x) w2s[i] = w2g[i];
    if (threadIdx.x < 128) u2s[threadIdx.x] = u2[threadIdx.x];
    __syncthreads();

    int w = threadIdx.x >> 5, lane = threadIdx.x & 31;
    int n0 = (blockIdx.x * 8 + w) * 4;
    if (n0 >= N_NODES) return;

    float hn[4];
    #pragma unroll
    for (int m = 0; m < 4; m++) {
        int n = n0 + m;
        float h = 0.f;
        if (n < N_NODES) {
            float cnt = fmaxf(g_cnt[n], 1.f);
            h = fmaxf(g_agg1[(size_t)n * 32 + lane] / cnt + b1[lane], 0.f);
        }
        hn[m] = h;
    }
    __syncwarp();

    // hu2[n] = h1[n] @ u2
    #pragma unroll
    for (int m = 0; m < 4; m++) {
        int n = n0 + m;
        if (n >= N_NODES) break;
        float a0 = hn[m] * u2s[lane * 4 + 0];
        float a1 = hn[m] * u2s[lane * 4 + 1];
        float a2 = hn[m] * u2s[lane * 4 + 2];
        float a3 = hn[m] * u2s[lane * 4 + 3];
        #pragma unroll
        for (int off = 16; off; off >>= 1) {
            a0 += __shfl_xor_sync(0xffffffffu, a0, off);
            a1 += __shfl_xor_sync(0xffffffffu, a1, off);
            a2 += __shfl_xor_sync(0xffffffffu, a2, off);
            a3 += __shfl_xor_sync(0xffffffffu, a3, off);
        }
        if (lane == 0) g_hu2[n] = make_float4(a0, a1, a2, a3);
    }

    float2 acc[4][4];
    #pragma unroll
    for (int m = 0; m < 4; m++)
        #pragma unroll
        for (int h = 0; h < 4; h++) acc[m][h] = make_float2(0.f, 0.f);

    #pragma unroll
    for (int k = 0; k < 32; k++) {
        float2 wk[4];
        #pragma unroll
        for (int h = 0; h < 4; h++) wk[h] = w2s[k * 128 + h * 32 + lane];
        #pragma unroll
        for (int m = 0; m < 4; m++) {
            float hk = __shfl_sync(0xffffffffu, hn[m], k);
            #pragma unroll
            for (int h = 0; h < 4; h++) {
                acc[m][h].x += hk * wk[h].x;
                acc[m][h].y += hk * wk[h].y;
            }
        }
    }
    #pragma unroll
    for (int m = 0; m < 4; m++) {
        int n = n0 + m;
        if (n < N_NODES) {
            #pragma unroll
            for (int h = 0; h < 4; h++)
                g_xw2h[(size_t)n * 128 + h * 32 + lane] = __float22half2_rn(acc[m][h]);
        }
    }
}

// ---------------- kernel D: conv2 edge pass (warp per edge, no shuffles) -----------
__global__ void k_conv2_edge(const int* __restrict__ ei,
                             const float* __restrict__ c2) {
    float cc0 = __ldg(&c2[0]), cc1 = __ldg(&c2[1]), cc2 = __ldg(&c2[2]), cc3 = __ldg(&c2[3]);
    int w = threadIdx.x >> 5, lane = threadIdx.x & 31;
    int e = blockIdx.x * 8 + w;
    if (e >= N_EDGES) return;

    int s = ei[e];
    int t = ei[N_EDGES + e];

    float4 a = g_hu2[s];
    float4 b = g_hu2[t];
    float l0 = a.x - b.x + cc0;
    float l1 = a.y - b.y + cc1;
    float l2 = a.z - b.z + cc2;
    float l3 = a.w - b.w + cc3;

    float m = fmaxf(fmaxf(l0, l1), fmaxf(l2, l3));
    float q0 = __expf(l0 - m), q1 = __expf(l1 - m), q2 = __expf(l2 - m), q3 = __expf(l3 - m);
    float inv = 1.f / (q0 + q1 + q2 + q3);
    q0 *= inv; q1 *= inv; q2 *= inv; q3 *= inv;

    const __half2* xr = g_xw2h + (size_t)s * 128;
    float2 v0 = __half22float2(xr[lane]);
    float2 v1 = __half22float2(xr[32 + lane]);
    float2 v2 = __half22float2(xr[64 + lane]);
    float2 v3 = __half22float2(xr[96 + lane]);
    float2 msg;
    msg.x = q0 * v0.x + q1 * v1.x + q2 * v2.x + q3 * v3.x;
    msg.y = q0 * v0.y + q1 * v1.y + q2 * v2.y + q3 * v3.y;
    atomicAdd((float2*)&g_agg2[(size_t)t * 64 + 2 * lane], msg);
}

// ---------------- kernel E: h2 epilogue + staged global pooling --------------------
__global__ void k_conv2_epi_pool(const float* __restrict__ b2,
                                 const int* __restrict__ batch) {
    __shared__ float pools[NGRAPHS * 64];
    __shared__ float gcnts[NGRAPHS];
    for (int i = threadIdx.x; i < NGRAPHS * 64; i += blockDim.x) pools[i] = 0.f;
    if (threadIdx.x < NGRAPHS) gcnts[threadIdx.x] = 0.f;
    __syncthreads();

    int w = threadIdx.x >> 5, lane = threadIdx.x & 31;
    int n = blockIdx.x * 8 + w;
    if (n < N_NODES) {
        float cnt = fmaxf(g_cnt[n], 1.f);
        int g = batch[n];
        float h0v = fmaxf(g_agg2[(size_t)n * 64 + lane]      / cnt + b2[lane],      0.f);
        float h1v = fmaxf(g_agg2[(size_t)n * 64 + 32 + lane] / cnt + b2[32 + lane], 0.f);
        atomicAdd(&pools[g * 64 + lane],      h0v);
        atomicAdd(&pools[g * 64 + 32 + lane], h1v);
        if (lane == 0) atomicAdd(&gcnts[g], 1.f);
    }
    __syncthreads();
    for (int i = threadIdx.x; i < NGRAPHS * 64; i += blockDim.x) atomicAdd(&g_pool[i], pools[i]);
    if (threadIdx.x < NGRAPHS) atomicAdd(&g_gcnt[threadIdx.x], gcnts[threadIdx.x]);
}

// ---------------- kernel F: head ---------------------------------------------------
__global__ void k_head(const float* __restrict__ fc1_w,
                       const float* __restrict__ fc1_b,
                       float* __restrict__ out) {
    int tid = threadIdx.x;
    if (tid < NGRAPHS * NCLASSES) {
        int g = tid / NCLASSES, j = tid % NCLASSES;
        float invn = 1.f / fmaxf(g_gcnt[g], 1.f);
        float acc = 0.f;
        #pragma unroll
        for (int c = 0; c < 64; c++) acc += g_pool[g * 64 + c] * fc1_w[c * NCLASSES + j];
        out[tid] = acc * invn + fc1_b[j];
    }
}

// ---------------- launch ------------------------------------------------------------
extern "C" void kernel_launch(void* const* d_in, const int* in_sizes, int n_in,
                              void* d_out, int out_size) {
    const float* x     = (const float*)d_in[0];
    const int*   ei    = (const int*)d_in[1];
    const int*   batch = (const int*)d_in[2];
    const float* fc0_w = (const float*)d_in[3];
    const float* fc0_b = (const float*)d_in[4];
    const float* u1    = (const float*)d_in[5];
    const float* c1    = (const float*)d_in[6];
    const float* w1    = (const float*)d_in[7];
    const float* b1    = (const float*)d_in[8];
    const float* u2    = (const float*)d_in[9];
    const float* c2    = (const float*)d_in[10];
    const float* w2    = (const float*)d_in[11];
    const float* b2    = (const float*)d_in[12];
    const float* fc1_w = (const float*)d_in[13];
    const float* fc1_b = (const float*)d_in[14];
    float* out = (float*)d_out;

    k_zero<<<2048, 256>>>();
    k_fc0_xw1<<<(N_NODES + 31) / 32, 256>>>(x, fc0_w, fc0_b, w1, u1);
    k_hu1<<<(N_NODES + 15) / 16, 256>>>(u1);          // authoritative hu1 (overwrites)
    k_conv1_edge<<<(N_EDGES + 15) / 16, 256>>>(ei, c1);
    k_conv1_epi_xw2<<<(N_NODES + 31) / 32, 256>>>(b1, w2, u2);
    k_conv2_edge<<<(N_EDGES + 7) / 8, 256>>>(ei, c2);
    k_conv2_epi_pool<<<(N_NODES + 7) / 8, 256>>>(b2, batch);
    k_head<<<1, 128>>>(fc1_w, fc1_b, out);
}

// round 5
// speedup vs baseline: 2.1000x; 1.2721x over previous
#include <cuda_runtime.h>
#include <cuda_fp16.h>
#include <cstdint>

#define N_NODES 50000
#define N_EDGES 800000
#define NGRAPHS 8
#define NCLASSES 10

__device__ __forceinline__ void red_add_v4(float* p, float a, float b, float c, float d) {
    asm volatile("red.global.add.v4.f32 [%0], {%1, %2, %3, %4};"
                 :: "l"(p), "f"(a), "f"(b), "f"(c), "f"(d) : "memory");
}

// ---------------- scratch (device globals) ----------------------------------------
__device__ float   g_h0  [N_NODES * 16];
__device__ float4  g_hu1 [N_NODES];        // h0 @ u1
__device__ __half2 g_xw1h[N_NODES * 64];   // h0@w1, [h*16+j] = head h, ch pair (2j,2j+1)
__device__ float   g_agg1[N_NODES * 32];
__device__ float   g_cnt [N_NODES];
__device__ float4  g_hu2 [N_NODES];        // h1 @ u2
__device__ __half2 g_xw2h[N_NODES * 128];  // h1@w2, [h*32+l] = head h, ch pair (2l,2l+1)
__device__ float   g_agg2[N_NODES * 64];
__device__ float   g_pool[NGRAPHS * 64];
__device__ float   g_gcnt[NGRAPHS];

// ---------------- zero scratch -----------------------------------------------------
__global__ void k_zero() {
    size_t idx = (size_t)blockIdx.x * blockDim.x + threadIdx.x;
    size_t stride = (size_t)gridDim.x * blockDim.x;
    for (size_t i = idx; i < (size_t)N_NODES * 64; i += stride) g_agg2[i] = 0.f;
    for (size_t i = idx; i < (size_t)N_NODES * 32; i += stride) g_agg1[i] = 0.f;
    for (size_t i = idx; i < (size_t)N_NODES;      i += stride) g_cnt[i]  = 0.f;
    if (idx < NGRAPHS * 64) g_pool[idx] = 0.f;
    if (idx < NGRAPHS)      g_gcnt[idx] = 0.f;
}

// ---------------- kernel A: h0 = relu(x@fc0+b); xw1 = h0@w1; hu1 = h0@u1 ----------
__global__ void k_fc0_xw1(const float* __restrict__ x,
                          const float* __restrict__ fc0_w,
                          const float* __restrict__ fc0_b,
                          const float* __restrict__ w1,
                          const float* __restrict__ u1) {
    __shared__ float2 w1s[16 * 64];        // 8KB
    __shared__ float  u1s[64];
    const float2* w1g = (const float2*)w1;
    for (int i = threadIdx.x; i < 16 * 64; i += blockDim.x) w1s[i] = w1g[i];
    if (threadIdx.x < 64) u1s[threadIdx.x] = u1[threadIdx.x];
    __syncthreads();

    int w = threadIdx.x >> 5, lane = threadIdx.x & 31;
    int n0 = (blockIdx.x * 8 + w) * 4;
    if (n0 >= N_NODES) return;

    float hn[4];
    #pragma unroll
    for (int m = 0; m < 4; m++) {
        int n = n0 + m;
        float v = 0.f;
        if (n < N_NODES && lane < 16) {
            v = fc0_b[lane];
            #pragma unroll
            for (int j = 0; j < 3; j++) v += x[n * 3 + j] * fc0_w[j * 16 + lane];
            v = fmaxf(v, 0.f);
            g_h0[n * 16 + lane] = v;
        }
        hn[m] = v;
    }
    __syncwarp();

    // hu1[n] = h0[n] @ u1 — lanes>=16 hold 0, xor-tree over 32 lanes = exact sum.
    #pragma unroll
    for (int m = 0; m < 4; m++) {
        int n = n0 + m;
        if (n >= N_NODES) break;
        int k = lane & 15;
        float a0 = hn[m] * u1s[k * 4 + 0];
        float a1 = hn[m] * u1s[k * 4 + 1];
        float a2 = hn[m] * u1s[k * 4 + 2];
        float a3 = hn[m] * u1s[k * 4 + 3];
        #pragma unroll
        for (int off = 16; off; off >>= 1) {
            a0 += __shfl_xor_sync(0xffffffffu, a0, off);
            a1 += __shfl_xor_sync(0xffffffffu, a1, off);
            a2 += __shfl_xor_sync(0xffffffffu, a2, off);
            a3 += __shfl_xor_sync(0xffffffffu, a3, off);
        }
        if (lane == 0) g_hu1[n] = make_float4(a0, a1, a2, a3);
    }

    float2 acc[4][2];
    #pragma unroll
    for (int m = 0; m < 4; m++) { acc[m][0] = make_float2(0.f, 0.f); acc[m][1] = make_float2(0.f, 0.f); }

    #pragma unroll
    for (int k = 0; k < 16; k++) {
        float2 wk0 = w1s[k * 64 + lane];
        float2 wk1 = w1s[k * 64 + 32 + lane];
        #pragma unroll
        for (int m = 0; m < 4; m++) {
            float hk = __shfl_sync(0xffffffffu, hn[m], k);
            acc[m][0].x += hk * wk0.x; acc[m][0].y += hk * wk0.y;
            acc[m][1].x += hk * wk1.x; acc[m][1].y += hk * wk1.y;
        }
    }
    #pragma unroll
    for (int m = 0; m < 4; m++) {
        int n = n0 + m;
        if (n < N_NODES) {
            g_xw1h[(size_t)n * 64 + lane]      = __float22half2_rn(acc[m][0]);
            g_xw1h[(size_t)n * 64 + 32 + lane] = __float22half2_rn(acc[m][1]);
        }
    }
}

// ---------------- kernel B: conv1 edge pass (4 edges/warp, 8 lanes each) -----------
// Lane j (<8) covers channels 4j..4j+3: pairs (2j, 2j+1) per head.
__global__ void k_conv1_edge(const int* __restrict__ ei,
                             const float* __restrict__ c1) {
    float cc0 = __ldg(&c1[0]), cc1 = __ldg(&c1[1]), cc2 = __ldg(&c1[2]), cc3 = __ldg(&c1[3]);
    int w = threadIdx.x >> 5, lane = threadIdx.x & 31;
    int sub = lane >> 3, j = lane & 7;
    int e = (blockIdx.x * 8 + w) * 4 + sub;
    if (e >= N_EDGES) return;

    int s = ei[e];
    int t = ei[N_EDGES + e];

    float4 a = g_hu1[s];
    float4 b = g_hu1[t];
    float l0 = a.x - b.x + cc0;
    float l1 = a.y - b.y + cc1;
    float l2 = a.z - b.z + cc2;
    float l3 = a.w - b.w + cc3;

    float m = fmaxf(fmaxf(l0, l1), fmaxf(l2, l3));
    float q0 = __expf(l0 - m), q1 = __expf(l1 - m), q2 = __expf(l2 - m), q3 = __expf(l3 - m);
    float inv = 1.f / (q0 + q1 + q2 + q3);
    q0 *= inv; q1 *= inv; q2 *= inv; q3 *= inv;

    const __half2* xr = g_xw1h + (size_t)s * 64;
    // head h pairs at [h*16 + 2j], [h*16 + 2j + 1]  -> one uint2 (two half2) per head
    float4 msg = make_float4(0.f, 0.f, 0.f, 0.f);
    float q[4] = {q0, q1, q2, q3};
    #pragma unroll
    for (int h = 0; h < 4; h++) {
        __half2 p0 = xr[h * 16 + 2 * j];
        __half2 p1 = xr[h * 16 + 2 * j + 1];
        float2 f0 = __half22float2(p0);
        float2 f1 = __half22float2(p1);
        msg.x += q[h] * f0.x; msg.y += q[h] * f0.y;
        msg.z += q[h] * f1.x; msg.w += q[h] * f1.y;
    }
    red_add_v4(&g_agg1[(size_t)t * 32 + 4 * j], msg.x, msg.y, msg.z, msg.w);
    if (j == 0) atomicAdd(&g_cnt[t], 1.0f);
}

// ---------------- kernel C: h1 epilogue + xw2 = h1@w2 + hu2 = h1@u2 ----------------
__global__ void k_conv1_epi_xw2(const float* __restrict__ b1,
                                const float* __restrict__ w2,
                                const float* __restrict__ u2) {
    __shared__ float2 w2s[32 * 128];       // 32KB
    __shared__ float  u2s[128];
    const float2* w2g = (const float2*)w2;
    for (int i = threadIdx.x; i < 32 * 128; i += blockDim.x) w2s[i] = w2g[i];
    if (threadIdx.x < 128) u2s[threadIdx.x] = u2[threadIdx.x];
    __syncthreads();

    int w = threadIdx.x >> 5, lane = threadIdx.x & 31;
    int n0 = (blockIdx.x * 8 + w) * 4;
    if (n0 >= N_NODES) return;

    float hn[4];
    #pragma unroll
    for (int m = 0; m < 4; m++) {
        int n = n0 + m;
        float h = 0.f;
        if (n < N_NODES) {
            float cnt = fmaxf(g_cnt[n], 1.f);
            h = fmaxf(g_agg1[(size_t)n * 32 + lane] / cnt + b1[lane], 0.f);
        }
        hn[m] = h;
    }
    __syncwarp();

    // hu2[n] = h1[n] @ u2
    #pragma unroll
    for (int m = 0; m < 4; m++) {
        int n = n0 + m;
        if (n >= N_NODES) break;
        float a0 = hn[m] * u2s[lane * 4 + 0];
        float a1 = hn[m] * u2s[lane * 4 + 1];
        float a2 = hn[m] * u2s[lane * 4 + 2];
        float a3 = hn[m] * u2s[lane * 4 + 3];
        #pragma unroll
        for (int off = 16; off; off >>= 1) {
            a0 += __shfl_xor_sync(0xffffffffu, a0, off);
            a1 += __shfl_xor_sync(0xffffffffu, a1, off);
            a2 += __shfl_xor_sync(0xffffffffu, a2, off);
            a3 += __shfl_xor_sync(0xffffffffu, a3, off);
        }
        if (lane == 0) g_hu2[n] = make_float4(a0, a1, a2, a3);
    }

    float2 acc[4][4];
    #pragma unroll
    for (int m = 0; m < 4; m++)
        #pragma unroll
        for (int h = 0; h < 4; h++) acc[m][h] = make_float2(0.f, 0.f);

    #pragma unroll
    for (int k = 0; k < 32; k++) {
        float2 wk[4];
        #pragma unroll
        for (int h = 0; h < 4; h++) wk[h] = w2s[k * 128 + h * 32 + lane];
        #pragma unroll
        for (int m = 0; m < 4; m++) {
            float hk = __shfl_sync(0xffffffffu, hn[m], k);
            #pragma unroll
            for (int h = 0; h < 4; h++) {
                acc[m][h].x += hk * wk[h].x;
                acc[m][h].y += hk * wk[h].y;
            }
        }
    }
    #pragma unroll
    for (int m = 0; m < 4; m++) {
        int n = n0 + m;
        if (n < N_NODES) {
            #pragma unroll
            for (int h = 0; h < 4; h++)
                g_xw2h[(size_t)n * 128 + h * 32 + lane] = __float22half2_rn(acc[m][h]);
        }
    }
}

// ---------------- kernel D: conv2 edge pass (2 edges/warp, 16 lanes each) ----------
// Lane j (<16) covers channels 4j..4j+3: pairs (2j, 2j+1) per head.
__global__ void k_conv2_edge(const int* __restrict__ ei,
                             const float* __restrict__ c2) {
    float cc0 = __ldg(&c2[0]), cc1 = __ldg(&c2[1]), cc2 = __ldg(&c2[2]), cc3 = __ldg(&c2[3]);
    int w = threadIdx.x >> 5, lane = threadIdx.x & 31;
    int sub = lane >> 4, j = lane & 15;
    int e = (blockIdx.x * 8 + w) * 2 + sub;
    if (e >= N_EDGES) return;

    int s = ei[e];
    int t = ei[N_EDGES + e];

    float4 a = g_hu2[s];
    float4 b = g_hu2[t];
    float l0 = a.x - b.x + cc0;
    float l1 = a.y - b.y + cc1;
    float l2 = a.z - b.z + cc2;
    float l3 = a.w - b.w + cc3;

    float m = fmaxf(fmaxf(l0, l1), fmaxf(l2, l3));
    float q0 = __expf(l0 - m), q1 = __expf(l1 - m), q2 = __expf(l2 - m), q3 = __expf(l3 - m);
    float inv = 1.f / (q0 + q1 + q2 + q3);
    q0 *= inv; q1 *= inv; q2 *= inv; q3 *= inv;

    const __half2* xr = g_xw2h + (size_t)s * 128;
    float4 msg = make_float4(0.f, 0.f, 0.f, 0.f);
    float q[4] = {q0, q1, q2, q3};
    #pragma unroll
    for (int h = 0; h < 4; h++) {
        __half2 p0 = xr[h * 32 + 2 * j];
        __half2 p1 = xr[h * 32 + 2 * j + 1];
        float2 f0 = __half22float2(p0);
        float2 f1 = __half22float2(p1);
        msg.x += q[h] * f0.x; msg.y += q[h] * f0.y;
        msg.z += q[h] * f1.x; msg.w += q[h] * f1.y;
    }
    red_add_v4(&g_agg2[(size_t)t * 64 + 4 * j], msg.x, msg.y, msg.z, msg.w);
}

// ---------------- kernel E: h2 epilogue + staged global pooling --------------------
__global__ void k_conv2_epi_pool(const float* __restrict__ b2,
                                 const int* __restrict__ batch) {
    __shared__ float pools[NGRAPHS * 64];
    __shared__ float gcnts[NGRAPHS];
    for (int i = threadIdx.x; i < NGRAPHS * 64; i += blockDim.x) pools[i] = 0.f;
    if (threadIdx.x < NGRAPHS) gcnts[threadIdx.x] = 0.f;
    __syncthreads();

    int w = threadIdx.x >> 5, lane = threadIdx.x & 31;
    int n = blockIdx.x * 8 + w;
    if (n < N_NODES) {
        float cnt = fmaxf(g_cnt[n], 1.f);
        int g = batch[n];
        float h0v = fmaxf(g_agg2[(size_t)n * 64 + lane]      / cnt + b2[lane],      0.f);
        float h1v = fmaxf(g_agg2[(size_t)n * 64 + 32 + lane] / cnt + b2[32 + lane], 0.f);
        atomicAdd(&pools[g * 64 + lane],      h0v);
        atomicAdd(&pools[g * 64 + 32 + lane], h1v);
        if (lane == 0) atomicAdd(&gcnts[g], 1.f);
    }
    __syncthreads();
    for (int i = threadIdx.x; i < NGRAPHS * 64; i += blockDim.x) atomicAdd(&g_pool[i], pools[i]);
    if (threadIdx.x < NGRAPHS) atomicAdd(&g_gcnt[threadIdx.x], gcnts[threadIdx.x]);
}

// ---------------- kernel F: head ---------------------------------------------------
__global__ void k_head(const float* __restrict__ fc1_w,
                       const float* __restrict__ fc1_b,
                       float* __restrict__ out) {
    int tid = threadIdx.x;
    if (tid < NGRAPHS * NCLASSES) {
        int g = tid / NCLASSES, j = tid % NCLASSES;
        float invn = 1.f / fmaxf(g_gcnt[g], 1.f);
        float acc = 0.f;
        #pragma unroll
        for (int c = 0; c < 64; c++) acc += g_pool[g * 64 + c] * fc1_w[c * NCLASSES + j];
        out[tid] = acc * invn + fc1_b[j];
    }
}

// ---------------- launch ------------------------------------------------------------
extern "C" void kernel_launch(void* const* d_in, const int* in_sizes, int n_in,
                              void* d_out, int out_size) {
    const float* x     = (const float*)d_in[0];
    const int*   ei    = (const int*)d_in[1];
    const int*   batch = (const int*)d_in[2];
    const float* fc0_w = (const float*)d_in[3];
    const float* fc0_b = (const float*)d_in[4];
    const float* u1    = (const float*)d_in[5];
    const float* c1    = (const float*)d_in[6];
    const float* w1    = (const float*)d_in[7];
    const float* b1    = (const float*)d_in[8];
    const float* u2    = (const float*)d_in[9];
    const float* c2    = (const float*)d_in[10];
    const float* w2    = (const float*)d_in[11];
    const float* b2    = (const float*)d_in[12];
    const float* fc1_w = (const float*)d_in[13];
    const float* fc1_b = (const float*)d_in[14];
    float* out = (float*)d_out;

    k_zero<<<2048, 256>>>();
    k_fc0_xw1<<<(N_NODES + 31) / 32, 256>>>(x, fc0_w, fc0_b, w1, u1);
    k_conv1_edge<<<(N_EDGES + 31) / 32, 256>>>(ei, c1);
    k_conv1_epi_xw2<<<(N_NODES + 31) / 32, 256>>>(b1, w2, u2);
    k_conv2_edge<<<(N_EDGES + 15) / 16, 256>>>(ei, c2);
    k_conv2_epi_pool<<<(N_NODES + 7) / 8, 256>>>(b2, batch);
    k_head<<<1, 128>>>(fc1_w, fc1_b, out);
}

// round 6
// speedup vs baseline: 2.1892x; 1.0425x over previous
#include <cuda_runtime.h>
#include <cuda_fp16.h>
#include <cstdint>

#define N_NODES 50000
#define N_EDGES 800000
#define NGRAPHS 8
#define NCLASSES 10

typedef unsigned long long ull;

__device__ __forceinline__ void red_add_v4(float* p, float a, float b, float c, float d) {
    asm volatile("red.global.add.v4.f32 [%0], {%1, %2, %3, %4};"
                 :: "l"(p), "f"(a), "f"(b), "f"(c), "f"(d) : "memory");
}
// packed fp32x2 FMA (Blackwell; PTX-only, ptxas never auto-fuses)
__device__ __forceinline__ ull f32x2_fma(ull a, ull b, ull c) {
    ull d;
    asm("fma.rn.f32x2 %0, %1, %2, %3;" : "=l"(d) : "l"(a), "l"(b), "l"(c));
    return d;
}
__device__ __forceinline__ ull pack2(float x) {
    ull r;
    asm("mov.b64 %0, {%1, %1};" : "=l"(r) : "f"(x));
    return r;
}
__device__ __forceinline__ float2 unpack2(ull v) {
    float2 f;
    asm("mov.b64 {%0, %1}, %2;" : "=f"(f.x), "=f"(f.y) : "l"(v));
    return f;
}

// ---------------- scratch (device globals) ----------------------------------------
__device__ float   g_h0  [N_NODES * 16];
__device__ float4  g_hu1 [N_NODES];        // h0 @ u1
__device__ __half2 g_xw1h[N_NODES * 64];   // h0@w1, [h*16+j] = head h, ch pair (2j,2j+1)
__device__ float   g_agg1[N_NODES * 32];
__device__ float   g_cnt [N_NODES];
__device__ float4  g_hu2 [N_NODES];        // h1 @ u2
__device__ __half2 g_xw2h[N_NODES * 128];  // h1@w2, [h*32+l] = head h, ch pair (2l,2l+1)
__device__ float   g_agg2[N_NODES * 64];
__device__ float   g_pool[NGRAPHS * 64];
__device__ float   g_gcnt[NGRAPHS];

// ---------------- zero scratch -----------------------------------------------------
__global__ void k_zero() {
    size_t idx = (size_t)blockIdx.x * blockDim.x + threadIdx.x;
    size_t stride = (size_t)gridDim.x * blockDim.x;
    for (size_t i = idx; i < (size_t)N_NODES * 64; i += stride) g_agg2[i] = 0.f;
    for (size_t i = idx; i < (size_t)N_NODES * 32; i += stride) g_agg1[i] = 0.f;
    for (size_t i = idx; i < (size_t)N_NODES;      i += stride) g_cnt[i]  = 0.f;
    if (idx < NGRAPHS * 64) g_pool[idx] = 0.f;
    if (idx < NGRAPHS)      g_gcnt[idx] = 0.f;
}

// ---------------- kernel A: h0 = relu(x@fc0+b); xw1 = h0@w1; hu1 = h0@u1 ----------
__global__ void k_fc0_xw1(const float* __restrict__ x,
                          const float* __restrict__ fc0_w,
                          const float* __restrict__ fc0_b,
                          const float* __restrict__ w1,
                          const float* __restrict__ u1) {
    __shared__ float2 w1s[16 * 64];        // 8KB
    __shared__ float  u1s[64];
    const float2* w1g = (const float2*)w1;
    for (int i = threadIdx.x; i < 16 * 64; i += blockDim.x) w1s[i] = w1g[i];
    if (threadIdx.x < 64) u1s[threadIdx.x] = u1[threadIdx.x];
    __syncthreads();

    int w = threadIdx.x >> 5, lane = threadIdx.x & 31;
    int n0 = (blockIdx.x * 8 + w) * 4;
    if (n0 >= N_NODES) return;

    float hn[4];
    #pragma unroll
    for (int m = 0; m < 4; m++) {
        int n = n0 + m;
        float v = 0.f;
        if (n < N_NODES && lane < 16) {
            v = fc0_b[lane];
            #pragma unroll
            for (int j = 0; j < 3; j++) v += x[n * 3 + j] * fc0_w[j * 16 + lane];
            v = fmaxf(v, 0.f);
            g_h0[n * 16 + lane] = v;
        }
        hn[m] = v;
    }
    __syncwarp();

    // hu1[n] = h0[n] @ u1 — lanes>=16 hold 0, xor-tree over 32 lanes = exact sum.
    #pragma unroll
    for (int m = 0; m < 4; m++) {
        int n = n0 + m;
        if (n >= N_NODES) break;
        int k = lane & 15;
        float a0 = hn[m] * u1s[k * 4 + 0];
        float a1 = hn[m] * u1s[k * 4 + 1];
        float a2 = hn[m] * u1s[k * 4 + 2];
        float a3 = hn[m] * u1s[k * 4 + 3];
        #pragma unroll
        for (int off = 16; off; off >>= 1) {
            a0 += __shfl_xor_sync(0xffffffffu, a0, off);
            a1 += __shfl_xor_sync(0xffffffffu, a1, off);
            a2 += __shfl_xor_sync(0xffffffffu, a2, off);
            a3 += __shfl_xor_sync(0xffffffffu, a3, off);
        }
        if (lane == 0) g_hu1[n] = make_float4(a0, a1, a2, a3);
    }

    const ull* w1u = (const ull*)w1s;
    ull acc[4][2];
    #pragma unroll
    for (int m = 0; m < 4; m++) { acc[m][0] = 0ull; acc[m][1] = 0ull; }

    #pragma unroll
    for (int k = 0; k < 16; k++) {
        ull wk0 = w1u[k * 64 + lane];
        ull wk1 = w1u[k * 64 + 32 + lane];
        #pragma unroll
        for (int m = 0; m < 4; m++) {
            ull hk = pack2(__shfl_sync(0xffffffffu, hn[m], k));
            acc[m][0] = f32x2_fma(hk, wk0, acc[m][0]);
            acc[m][1] = f32x2_fma(hk, wk1, acc[m][1]);
        }
    }
    #pragma unroll
    for (int m = 0; m < 4; m++) {
        int n = n0 + m;
        if (n < N_NODES) {
            g_xw1h[(size_t)n * 64 + lane]      = __float22half2_rn(unpack2(acc[m][0]));
            g_xw1h[(size_t)n * 64 + 32 + lane] = __float22half2_rn(unpack2(acc[m][1]));
        }
    }
}

// ---------------- kernel B: conv1 edge pass (4 edges/warp, 8 lanes each) -----------
__global__ void k_conv1_edge(const int* __restrict__ ei,
                             const float* __restrict__ c1) {
    float cc0 = __ldg(&c1[0]), cc1 = __ldg(&c1[1]), cc2 = __ldg(&c1[2]), cc3 = __ldg(&c1[3]);
    int w = threadIdx.x >> 5, lane = threadIdx.x & 31;
    int sub = lane >> 3, j = lane & 7;
    int e = (blockIdx.x * 8 + w) * 4 + sub;
    if (e >= N_EDGES) return;

    int s = ei[e];
    int t = ei[N_EDGES + e];

    float4 a = g_hu1[s];
    float4 b = g_hu1[t];
    float l0 = a.x - b.x + cc0;
    float l1 = a.y - b.y + cc1;
    float l2 = a.z - b.z + cc2;
    float l3 = a.w - b.w + cc3;

    float m = fmaxf(fmaxf(l0, l1), fmaxf(l2, l3));
    float q0 = __expf(l0 - m), q1 = __expf(l1 - m), q2 = __expf(l2 - m), q3 = __expf(l3 - m);
    float inv = 1.f / (q0 + q1 + q2 + q3);
    float q[4] = {q0 * inv, q1 * inv, q2 * inv, q3 * inv};

    // head h pairs at half2 idx [h*16 + 2j], [h*16+2j+1] -> uint2 idx h*8 + j
    const uint2* xr2 = (const uint2*)(g_xw1h + (size_t)s * 64);
    ull m01 = 0ull, m23 = 0ull;
    #pragma unroll
    for (int h = 0; h < 4; h++) {
        uint2 p = xr2[h * 8 + j];
        float2 f0 = __half22float2(*(__half2*)&p.x);
        float2 f1 = __half22float2(*(__half2*)&p.y);
        ull qh = pack2(q[h]);
        m01 = f32x2_fma(qh, *(ull*)&f0, m01);
        m23 = f32x2_fma(qh, *(ull*)&f1, m23);
    }
    float2 r01 = unpack2(m01), r23 = unpack2(m23);
    red_add_v4(&g_agg1[(size_t)t * 32 + 4 * j], r01.x, r01.y, r23.x, r23.y);
    if (j == 0) atomicAdd(&g_cnt[t], 1.0f);
}

// ---------------- kernel C: h1 epilogue + xw2 = h1@w2 + hu2 = h1@u2 ----------------
__global__ void k_conv1_epi_xw2(const float* __restrict__ b1,
                                const float* __restrict__ w2,
                                const float* __restrict__ u2) {
    __shared__ float2 w2s[32 * 128];       // 32KB
    __shared__ float  u2s[128];
    const float2* w2g = (const float2*)w2;
    for (int i = threadIdx.x; i < 32 * 128; i += blockDim.x) w2s[i] = w2g[i];
    if (threadIdx.x < 128) u2s[threadIdx.x] = u2[threadIdx.x];
    __syncthreads();

    int w = threadIdx.x >> 5, lane = threadIdx.x & 31;
    int n0 = (blockIdx.x * 8 + w) * 4;
    if (n0 >= N_NODES) return;

    float hn[4];
    #pragma unroll
    for (int m = 0; m < 4; m++) {
        int n = n0 + m;
        float h = 0.f;
        if (n < N_NODES) {
            float cnt = fmaxf(g_cnt[n], 1.f);
            h = fmaxf(g_agg1[(size_t)n * 32 + lane] / cnt + b1[lane], 0.f);
        }
        hn[m] = h;
    }
    __syncwarp();

    // hu2[n] = h1[n] @ u2
    #pragma unroll
    for (int m = 0; m < 4; m++) {
        int n = n0 + m;
        if (n >= N_NODES) break;
        float a0 = hn[m] * u2s[lane * 4 + 0];
        float a1 = hn[m] * u2s[lane * 4 + 1];
        float a2 = hn[m] * u2s[lane * 4 + 2];
        float a3 = hn[m] * u2s[lane * 4 + 3];
        #pragma unroll
        for (int off = 16; off; off >>= 1) {
            a0 += __shfl_xor_sync(0xffffffffu, a0, off);
            a1 += __shfl_xor_sync(0xffffffffu, a1, off);
            a2 += __shfl_xor_sync(0xffffffffu, a2, off);
            a3 += __shfl_xor_sync(0xffffffffu, a3, off);
        }
        if (lane == 0) g_hu2[n] = make_float4(a0, a1, a2, a3);
    }

    const ull* w2u = (const ull*)w2s;
    ull acc[4][4];
    #pragma unroll
    for (int m = 0; m < 4; m++)
        #pragma unroll
        for (int h = 0; h < 4; h++) acc[m][h] = 0ull;

    #pragma unroll
    for (int k = 0; k < 32; k++) {
        ull wk[4];
        #pragma unroll
        for (int h = 0; h < 4; h++) wk[h] = w2u[k * 128 + h * 32 + lane];
        #pragma unroll
        for (int m = 0; m < 4; m++) {
            ull hk = pack2(__shfl_sync(0xffffffffu, hn[m], k));
            #pragma unroll
            for (int h = 0; h < 4; h++)
                acc[m][h] = f32x2_fma(hk, wk[h], acc[m][h]);
        }
    }
    #pragma unroll
    for (int m = 0; m < 4; m++) {
        int n = n0 + m;
        if (n < N_NODES) {
            #pragma unroll
            for (int h = 0; h < 4; h++)
                g_xw2h[(size_t)n * 128 + h * 32 + lane] = __float22half2_rn(unpack2(acc[m][h]));
        }
    }
}

// ---------------- kernel D: conv2 edge pass (2 edges/warp, 16 lanes each) ----------
__global__ void k_conv2_edge(const int* __restrict__ ei,
                             const float* __restrict__ c2) {
    float cc0 = __ldg(&c2[0]), cc1 = __ldg(&c2[1]), cc2 = __ldg(&c2[2]), cc3 = __ldg(&c2[3]);
    int w = threadIdx.x >> 5, lane = threadIdx.x & 31;
    int sub = lane >> 4, j = lane & 15;
    int e = (blockIdx.x * 8 + w) * 2 + sub;
    if (e >= N_EDGES) return;

    int s = ei[e];
    int t = ei[N_EDGES + e];

    float4 a = g_hu2[s];
    float4 b = g_hu2[t];
    float l0 = a.x - b.x + cc0;
    float l1 = a.y - b.y + cc1;
    float l2 = a.z - b.z + cc2;
    float l3 = a.w - b.w + cc3;

    float m = fmaxf(fmaxf(l0, l1), fmaxf(l2, l3));
    float q0 = __expf(l0 - m), q1 = __expf(l1 - m), q2 = __expf(l2 - m), q3 = __expf(l3 - m);
    float inv = 1.f / (q0 + q1 + q2 + q3);
    float q[4] = {q0 * inv, q1 * inv, q2 * inv, q3 * inv};

    // head h pairs at half2 idx [h*32 + 2j], [h*32+2j+1] -> uint2 idx h*16 + j
    const uint2* xr2 = (const uint2*)(g_xw2h + (size_t)s * 128);
    ull m01 = 0ull, m23 = 0ull;
    #pragma unroll
    for (int h = 0; h < 4; h++) {
        uint2 p = xr2[h * 16 + j];
        float2 f0 = __half22float2(*(__half2*)&p.x);
        float2 f1 = __half22float2(*(__half2*)&p.y);
        ull qh = pack2(q[h]);
        m01 = f32x2_fma(qh, *(ull*)&f0, m01);
        m23 = f32x2_fma(qh, *(ull*)&f1, m23);
    }
    float2 r01 = unpack2(m01), r23 = unpack2(m23);
    red_add_v4(&g_agg2[(size_t)t * 64 + 4 * j], r01.x, r01.y, r23.x, r23.y);
}

// ---------------- kernel E: h2 epilogue + staged global pooling --------------------
__global__ void k_conv2_epi_pool(const float* __restrict__ b2,
                                 const int* __restrict__ batch) {
    __shared__ float pools[NGRAPHS * 64];
    __shared__ float gcnts[NGRAPHS];
    for (int i = threadIdx.x; i < NGRAPHS * 64; i += blockDim.x) pools[i] = 0.f;
    if (threadIdx.x < NGRAPHS) gcnts[threadIdx.x] = 0.f;
    __syncthreads();

    int w = threadIdx.x >> 5, lane = threadIdx.x & 31;
    int n = blockIdx.x * 8 + w;
    if (n < N_NODES) {
        float cnt = fmaxf(g_cnt[n], 1.f);
        int g = batch[n];
        float h0v = fmaxf(g_agg2[(size_t)n * 64 + lane]      / cnt + b2[lane],      0.f);
        float h1v = fmaxf(g_agg2[(size_t)n * 64 + 32 + lane] / cnt + b2[32 + lane], 0.f);
        atomicAdd(&pools[g * 64 + lane],      h0v);
        atomicAdd(&pools[g * 64 + 32 + lane], h1v);
        if (lane == 0) atomicAdd(&gcnts[g], 1.f);
    }
    __syncthreads();
    for (int i = threadIdx.x; i < NGRAPHS * 64; i += blockDim.x) atomicAdd(&g_pool[i], pools[i]);
    if (threadIdx.x < NGRAPHS) atomicAdd(&g_gcnt[threadIdx.x], gcnts[threadIdx.x]);
}

// ---------------- kernel F: head ---------------------------------------------------
__global__ void k_head(const float* __restrict__ fc1_w,
                       const float* __restrict__ fc1_b,
                       float* __restrict__ out) {
    int tid = threadIdx.x;
    if (tid < NGRAPHS * NCLASSES) {
        int g = tid / NCLASSES, j = tid % NCLASSES;
        float invn = 1.f / fmaxf(g_gcnt[g], 1.f);
        float acc = 0.f;
        #pragma unroll
        for (int c = 0; c < 64; c++) acc += g_pool[g * 64 + c] * fc1_w[c * NCLASSES + j];
        out[tid] = acc * invn + fc1_b[j];
    }
}

// ---------------- launch ------------------------------------------------------------
extern "C" void kernel_launch(void* const* d_in, const int* in_sizes, int n_in,
                              void* d_out, int out_size) {
    const float* x     = (const float*)d_in[0];
    const int*   ei    = (const int*)d_in[1];
    const int*   batch = (const int*)d_in[2];
    const float* fc0_w = (const float*)d_in[3];
    const float* fc0_b = (const float*)d_in[4];
    const float* u1    = (const float*)d_in[5];
    const float* c1    = (const float*)d_in[6];
    const float* w1    = (const float*)d_in[7];
    const float* b1    = (const float*)d_in[8];
    const float* u2    = (const float*)d_in[9];
    const float* c2    = (const float*)d_in[10];
    const float* w2    = (const float*)d_in[11];
    const float* b2    = (const float*)d_in[12];
    const float* fc1_w = (const float*)d_in[13];
    const float* fc1_b = (const float*)d_in[14];
    float* out = (float*)d_out;

    k_zero<<<2048, 256>>>();
    k_fc0_xw1<<<(N_NODES + 31) / 32, 256>>>(x, fc0_w, fc0_b, w1, u1);
    k_conv1_edge<<<(N_EDGES + 31) / 32, 256>>>(ei, c1);
    k_conv1_epi_xw2<<<(N_NODES + 31) / 32, 256>>>(b1, w2, u2);
    k_conv2_edge<<<(N_EDGES + 15) / 16, 256>>>(ei, c2);
    k_conv2_epi_pool<<<(N_NODES + 7) / 8, 256>>>(b2, batch);
    k_head<<<1, 128>>>(fc1_w, fc1_b, out);
}